// round 11
// baseline (speedup 1.0000x reference)
#include <cuda_runtime.h>

// ---------------------------------------------------------------------------
// OTPE single timestep.
// Inputs (metadata order): x[8192], W[8192,4096], u[4096], E[8192,4096],
//                          R_hat[8192,4096], g_bar[4096], ratio[1]
// Output (flattened tuple): s[4096], u_new[4096], E_new[8192*4096],
//                           R_new[8192*4096], g_bar_new[4096], ratio_new[1]
// ---------------------------------------------------------------------------

#define N_IN   8192
#define N_OUT  4096
#define N_OUTV (N_OUT / 4)               // 1024 float4 per row
// sigmoid(2.0) in fp32
#define SIG_TAU 0.88079707797788231f

#define NSPLIT 256
#define ROWS_PER_SPLIT (N_IN / NSPLIT)     // 32

#define GEMV_STAGES 8

// scratch (device globals; no allocation allowed)
__device__ __align__(16) float g_part[NSPLIT * N_OUT];    // 4 MB
__device__ __align__(16) float g_sg[N_OUT];

// ---------------------------------------------------------------------------
// K1: split-K GEMV via cp.async (LDGSTS .cg) 8-stage pipeline.
// grid (4, 256) = 1024 blocks, block 256. R8 config exactly (no PDL trigger
// — R10 showed even the K1-only early trigger costs ~0.7us).
// ---------------------------------------------------------------------------
__global__ void __launch_bounds__(256)
otpe_gemv_partial(const float4* __restrict__ W4, const float* __restrict__ x) {
    __shared__ __align__(16) float4 tile[GEMV_STAGES][256];
    __shared__ float sx[ROWS_PER_SPLIT];

    const int t     = threadIdx.x;
    const int split = blockIdx.y;
    const int r0    = split * ROWS_PER_SPLIT;
    const int colv  = blockIdx.x * 256 + t;

    if (t < ROWS_PER_SPLIT)
        sx[t] = x[r0 + t];
    __syncthreads();

    const float4* Wg = W4 + (size_t)r0 * N_OUTV + colv;

#pragma unroll
    for (int s = 0; s < GEMV_STAGES; ++s) {
        unsigned dst = (unsigned)__cvta_generic_to_shared(&tile[s][t]);
        asm volatile("cp.async.cg.shared.global [%0], [%1], 16;\n"
                     :: "r"(dst), "l"(Wg + (size_t)s * N_OUTV));
        asm volatile("cp.async.commit_group;\n");
    }

    float4 A = make_float4(0.f, 0.f, 0.f, 0.f);
#pragma unroll
    for (int r = 0; r < ROWS_PER_SPLIT; ++r) {
        asm volatile("cp.async.wait_group %0;\n" :: "n"(GEMV_STAGES - 1) : "memory");
        const float4 w  = tile[r & (GEMV_STAGES - 1)][t];
        const float  xr = sx[r];
        A.x = fmaf(xr, w.x, A.x);
        A.y = fmaf(xr, w.y, A.y);
        A.z = fmaf(xr, w.z, A.z);
        A.w = fmaf(xr, w.w, A.w);

        const int rn = r + GEMV_STAGES;
        if (rn < ROWS_PER_SPLIT) {
            unsigned dst = (unsigned)__cvta_generic_to_shared(
                &tile[r & (GEMV_STAGES - 1)][t]);
            asm volatile("cp.async.cg.shared.global [%0], [%1], 16;\n"
                         :: "r"(dst), "l"(Wg + (size_t)rn * N_OUTV));
        }
        asm volatile("cp.async.commit_group;\n");
    }

    reinterpret_cast<float4*>(g_part)[(size_t)split * N_OUTV + colv] = A;
}

// ---------------------------------------------------------------------------
// K2: fused reduce (256 splits) + per-column post. grid 64, block 256.
// PDL secondary (R8 config): prefetch inputs, wait on K1, read g_part.
// ---------------------------------------------------------------------------
__global__ void __launch_bounds__(256)
otpe_reduce_post(const float* __restrict__ u,
                 const float* __restrict__ g_bar,
                 const float* __restrict__ ratio,
                 float* __restrict__ out_s,
                 float* __restrict__ out_u,
                 float* __restrict__ out_gbar,
                 float* __restrict__ out_ratio) {
    __shared__ float sums[4][64];

    const int c   = threadIdx.x & 63;        // column within block
    const int k   = threadIdx.x >> 6;        // split group 0..3
    const int col = blockIdx.x * 64 + c;
    const int s0  = k * 64;
    const int j   = blockIdx.x * 64 + threadIdx.x;   // valid if tid<64

    // dependency-free prefetch (inputs only)
    float u_j = 0.f, gb_j = 0.f, ratio_in = 0.f;
    if (threadIdx.x < 64) {
        u_j      = u[j];
        gb_j     = g_bar[j];
        ratio_in = ratio[0];
    }

    cudaGridDependencySynchronize();   // K1's g_part now visible

    float a0 = 0.f, a1 = 0.f, a2 = 0.f, a3 = 0.f;
#pragma unroll
    for (int s = 0; s < 64; s += 4) {
        a0 += g_part[(size_t)(s0 + s + 0) * N_OUT + col];
        a1 += g_part[(size_t)(s0 + s + 1) * N_OUT + col];
        a2 += g_part[(size_t)(s0 + s + 2) * N_OUT + col];
        a3 += g_part[(size_t)(s0 + s + 3) * N_OUT + col];
    }
    sums[k][c] = (a0 + a1) + (a2 + a3);
    __syncthreads();

    if (threadIdx.x < 64) {
        const float u_pre = fmaf(SIG_TAU, u_j,
            ((sums[0][threadIdx.x] + sums[1][threadIdx.x]) +
             (sums[2][threadIdx.x] + sums[3][threadIdx.x])));

        const float spike = (u_pre >= 1.0f) ? 1.0f : 0.0f;
        const float t  = fmaf(10.0f, fabsf(u_pre - 1.0f), 1.0f);
        const float sg = 1.0f / (t * t);

        g_sg[j]  = sg;
        out_s[j] = spike;
        out_u[j] = u_pre - spike;          // soft reset (V_TH = 1)

        const float r0        = SIG_TAU * ratio_in;
        const float ratio_new = r0 + 1.0f;
        const float r         = r0 / ratio_new;
        // ds_du_prev / sig_tau == sg
        out_gbar[j] = fmaf(r, gb_j, (1.0f - r) * sg);

        if (j == 0) out_ratio[0] = ratio_new;
    }
}

// ---------------------------------------------------------------------------
// K3: fused E/R update. ISOLATED CHANGE vs R8: 2 float4-pairs per thread,
// all 4 big loads front-batched (higher MLP_p1), plain ld/st (no hints).
// R_new = sig*R_hat + sg*E_new. grid 16384, block 256.
// PDL secondary: prefetch before waiting on K2; read g_sg after.
// ---------------------------------------------------------------------------
__global__ void __launch_bounds__(256)
otpe_big_elem(const float4* __restrict__ E,
              const float4* __restrict__ R,
              const float*  __restrict__ x,
              float4* __restrict__ Eo,
              float4* __restrict__ Ro) {
    // block covers 512 consecutive float4; thread handles v and v+256
    const long long v0 = (long long)blockIdx.x * 512 + threadIdx.x;
    const long long v1 = v0 + 256;
    const int row0  = (int)(v0 >> 10);       // 1024 float4 per row
    const int colv0 = (int)(v0 & 1023);
    const int row1  = (int)(v1 >> 10);
    const int colv1 = (int)(v1 & 1023);

    // dependency-free prefetch: 4 LDG.128 front-batched + 2 scalar
    const float4 e0  = E[v0];
    const float4 e1  = E[v1];
    const float4 rr0 = R[v0];
    const float4 rr1 = R[v1];
    const float  xi0 = __ldg(&x[row0]);
    const float  xi1 = __ldg(&x[row1]);

    cudaGridDependencySynchronize();   // K2's g_sg now visible

    const float4 sg0 = reinterpret_cast<const float4*>(g_sg)[colv0];
    const float4 sg1 = reinterpret_cast<const float4*>(g_sg)[colv1];

    float4 eo0, ro0, eo1, ro1;
    eo0.x = fmaf(SIG_TAU, e0.x, xi0);
    eo0.y = fmaf(SIG_TAU, e0.y, xi0);
    eo0.z = fmaf(SIG_TAU, e0.z, xi0);
    eo0.w = fmaf(SIG_TAU, e0.w, xi0);
    eo1.x = fmaf(SIG_TAU, e1.x, xi1);
    eo1.y = fmaf(SIG_TAU, e1.y, xi1);
    eo1.z = fmaf(SIG_TAU, e1.z, xi1);
    eo1.w = fmaf(SIG_TAU, e1.w, xi1);

    ro0.x = fmaf(sg0.x, eo0.x, SIG_TAU * rr0.x);
    ro0.y = fmaf(sg0.y, eo0.y, SIG_TAU * rr0.y);
    ro0.z = fmaf(sg0.z, eo0.z, SIG_TAU * rr0.z);
    ro0.w = fmaf(sg0.w, eo0.w, SIG_TAU * rr0.w);
    ro1.x = fmaf(sg1.x, eo1.x, SIG_TAU * rr1.x);
    ro1.y = fmaf(sg1.y, eo1.y, SIG_TAU * rr1.y);
    ro1.z = fmaf(sg1.z, eo1.z, SIG_TAU * rr1.z);
    ro1.w = fmaf(sg1.w, eo1.w, SIG_TAU * rr1.w);

    Eo[v0] = eo0;
    Eo[v1] = eo1;
    Ro[v0] = ro0;
    Ro[v1] = ro1;
}

// ---------------------------------------------------------------------------
extern "C" void kernel_launch(void* const* d_in, const int* in_sizes, int n_in,
                              void* d_out, int out_size) {
    const float* x     = (const float*)d_in[0];
    const float* W     = (const float*)d_in[1];
    const float* u     = (const float*)d_in[2];
    const float* E     = (const float*)d_in[3];
    const float* R     = (const float*)d_in[4];
    const float* g_bar = (const float*)d_in[5];
    const float* ratio = (const float*)d_in[6];

    float* out       = (float*)d_out;
    float* out_s     = out;
    float* out_u     = out + N_OUT;
    float* out_E     = out + 2 * N_OUT;
    float* out_R     = out_E + (size_t)N_IN * N_OUT;
    float* out_gbar  = out_R + (size_t)N_IN * N_OUT;
    float* out_ratio = out_gbar + N_OUT;

    // K1: normal launch (R8 config)
    otpe_gemv_partial<<<dim3(N_OUTV / 256, NSPLIT), 256>>>((const float4*)W, x);

    // K2, K3: programmatic dependent launches (implicit completion triggers).
    cudaLaunchAttribute pdl[1];
    pdl[0].id = cudaLaunchAttributeProgrammaticStreamSerialization;
    pdl[0].val.programmaticStreamSerializationAllowed = 1;

    {
        cudaLaunchConfig_t cfg = {};
        cfg.gridDim  = dim3(N_OUT / 64);
        cfg.blockDim = dim3(256);
        cfg.stream   = 0;
        cfg.attrs    = pdl;
        cfg.numAttrs = 1;
        cudaLaunchKernelEx(&cfg, otpe_reduce_post, u, g_bar, ratio,
                           out_s, out_u, out_gbar, out_ratio);
    }
    {
        const long long nvec = (long long)N_IN * N_OUT / 4;   // 8388608
        cudaLaunchConfig_t cfg = {};
        cfg.gridDim  = dim3((unsigned)(nvec / 512));
        cfg.blockDim = dim3(256);
        cfg.stream   = 0;
        cfg.attrs    = pdl;
        cfg.numAttrs = 1;
        cudaLaunchKernelEx(&cfg, otpe_big_elem,
                           (const float4*)E, (const float4*)R, x,
                           (float4*)out_E, (float4*)out_R);
    }
}

// round 12
// speedup vs baseline: 1.0027x; 1.0027x over previous
#include <cuda_runtime.h>

// ---------------------------------------------------------------------------
// OTPE single timestep — converged configuration (R8).
// Inputs (metadata order): x[8192], W[8192,4096], u[4096], E[8192,4096],
//                          R_hat[8192,4096], g_bar[4096], ratio[1]
// Output (flattened tuple): s[4096], u_new[4096], E_new[8192*4096],
//                           R_new[8192*4096], g_bar_new[4096], ratio_new[1]
//
// Structure: K1 split-K GEMV (cp.async pipeline, read-stream cap ~5.4TB/s),
// K2 fused deterministic reduce + LIF post (PDL, prefetch-then-sync),
// K3 fused E/R elementwise (float4, 1/thread, ~82% DRAM; PDL).
// R_new uses the identity sg*(sig*E + x) = ds_du_prev*E + x*sg = sg*E_new.
// ---------------------------------------------------------------------------

#define N_IN   8192
#define N_OUT  4096
#define N_OUTV (N_OUT / 4)               // 1024 float4 per row
// sigmoid(2.0) in fp32
#define SIG_TAU 0.88079707797788231f

#define NSPLIT 256
#define ROWS_PER_SPLIT (N_IN / NSPLIT)     // 32

#define GEMV_STAGES 8

// scratch (device globals; no allocation allowed)
__device__ __align__(16) float g_part[NSPLIT * N_OUT];    // 4 MB
__device__ __align__(16) float g_sg[N_OUT];

// ---------------------------------------------------------------------------
// K1: split-K GEMV via cp.async (LDGSTS .cg) 8-stage pipeline.
// grid (4, 256) = 1024 blocks, block 256, 32KB smem. Thread t stages and
// consumes only its own float4 column -> no __syncthreads in the mainloop.
// ---------------------------------------------------------------------------
__global__ void __launch_bounds__(256)
otpe_gemv_partial(const float4* __restrict__ W4, const float* __restrict__ x) {
    __shared__ __align__(16) float4 tile[GEMV_STAGES][256];
    __shared__ float sx[ROWS_PER_SPLIT];

    const int t     = threadIdx.x;
    const int split = blockIdx.y;
    const int r0    = split * ROWS_PER_SPLIT;
    const int colv  = blockIdx.x * 256 + t;

    if (t < ROWS_PER_SPLIT)
        sx[t] = x[r0 + t];
    __syncthreads();

    const float4* Wg = W4 + (size_t)r0 * N_OUTV + colv;

#pragma unroll
    for (int s = 0; s < GEMV_STAGES; ++s) {
        unsigned dst = (unsigned)__cvta_generic_to_shared(&tile[s][t]);
        asm volatile("cp.async.cg.shared.global [%0], [%1], 16;\n"
                     :: "r"(dst), "l"(Wg + (size_t)s * N_OUTV));
        asm volatile("cp.async.commit_group;\n");
    }

    float4 A = make_float4(0.f, 0.f, 0.f, 0.f);
#pragma unroll
    for (int r = 0; r < ROWS_PER_SPLIT; ++r) {
        asm volatile("cp.async.wait_group %0;\n" :: "n"(GEMV_STAGES - 1) : "memory");
        const float4 w  = tile[r & (GEMV_STAGES - 1)][t];
        const float  xr = sx[r];
        A.x = fmaf(xr, w.x, A.x);
        A.y = fmaf(xr, w.y, A.y);
        A.z = fmaf(xr, w.z, A.z);
        A.w = fmaf(xr, w.w, A.w);

        const int rn = r + GEMV_STAGES;
        if (rn < ROWS_PER_SPLIT) {
            unsigned dst = (unsigned)__cvta_generic_to_shared(
                &tile[r & (GEMV_STAGES - 1)][t]);
            asm volatile("cp.async.cg.shared.global [%0], [%1], 16;\n"
                         :: "r"(dst), "l"(Wg + (size_t)rn * N_OUTV));
        }
        asm volatile("cp.async.commit_group;\n");
    }

    reinterpret_cast<float4*>(g_part)[(size_t)split * N_OUTV + colv] = A;
}

// ---------------------------------------------------------------------------
// K2: fused reduce (256 splits) + per-column post. grid 64, block 256.
// PDL secondary: prefetch u/g_bar/ratio, THEN wait on K1, THEN read g_part.
// Fixed-order smem combine keeps the reduction deterministic.
// ---------------------------------------------------------------------------
__global__ void __launch_bounds__(256)
otpe_reduce_post(const float* __restrict__ u,
                 const float* __restrict__ g_bar,
                 const float* __restrict__ ratio,
                 float* __restrict__ out_s,
                 float* __restrict__ out_u,
                 float* __restrict__ out_gbar,
                 float* __restrict__ out_ratio) {
    __shared__ float sums[4][64];

    const int c   = threadIdx.x & 63;        // column within block
    const int k   = threadIdx.x >> 6;        // split group 0..3
    const int col = blockIdx.x * 64 + c;
    const int s0  = k * 64;
    const int j   = blockIdx.x * 64 + threadIdx.x;   // valid if tid<64

    // dependency-free prefetch (inputs only)
    float u_j = 0.f, gb_j = 0.f, ratio_in = 0.f;
    if (threadIdx.x < 64) {
        u_j      = u[j];
        gb_j     = g_bar[j];
        ratio_in = ratio[0];
    }

    cudaGridDependencySynchronize();   // K1's g_part now visible

    float a0 = 0.f, a1 = 0.f, a2 = 0.f, a3 = 0.f;
#pragma unroll
    for (int s = 0; s < 64; s += 4) {
        a0 += g_part[(size_t)(s0 + s + 0) * N_OUT + col];
        a1 += g_part[(size_t)(s0 + s + 1) * N_OUT + col];
        a2 += g_part[(size_t)(s0 + s + 2) * N_OUT + col];
        a3 += g_part[(size_t)(s0 + s + 3) * N_OUT + col];
    }
    sums[k][c] = (a0 + a1) + (a2 + a3);
    __syncthreads();

    if (threadIdx.x < 64) {
        const float u_pre = fmaf(SIG_TAU, u_j,
            ((sums[0][threadIdx.x] + sums[1][threadIdx.x]) +
             (sums[2][threadIdx.x] + sums[3][threadIdx.x])));

        const float spike = (u_pre >= 1.0f) ? 1.0f : 0.0f;
        const float t  = fmaf(10.0f, fabsf(u_pre - 1.0f), 1.0f);
        const float sg = 1.0f / (t * t);

        g_sg[j]  = sg;
        out_s[j] = spike;
        out_u[j] = u_pre - spike;          // soft reset (V_TH = 1)

        const float r0        = SIG_TAU * ratio_in;
        const float ratio_new = r0 + 1.0f;
        const float r         = r0 / ratio_new;
        // ds_du_prev / sig_tau == sg
        out_gbar[j] = fmaf(r, gb_j, (1.0f - r) * sg);

        if (j == 0) out_ratio[0] = ratio_new;
    }
}

// ---------------------------------------------------------------------------
// K3: fused E/R update, float4, 1 per thread (measured optimum: 82% DRAM).
// PDL secondary: prefetch E/R_hat/x (input-only, no hazard) before waiting
// on K2; read g_sg after. R_new = sig*R_hat + sg*E_new.
// grid 32768, block 256.
// ---------------------------------------------------------------------------
__global__ void __launch_bounds__(256)
otpe_big_elem(const float4* __restrict__ E,
              const float4* __restrict__ R,
              const float*  __restrict__ x,
              float4* __restrict__ Eo,
              float4* __restrict__ Ro) {
    const long long v = (long long)blockIdx.x * 256 + threadIdx.x;
    const int row  = (int)(v >> 10);        // 1024 float4 per row
    const int colv = (int)(v & 1023);

    // dependency-free prefetch (inputs only)
    const float  xi = __ldg(&x[row]);
    const float4 e  = E[v];
    const float4 rr = R[v];

    cudaGridDependencySynchronize();   // K2's g_sg now visible

    const float4 sg4 = reinterpret_cast<const float4*>(g_sg)[colv];

    float4 eo, ro;
    eo.x = fmaf(SIG_TAU, e.x, xi);
    eo.y = fmaf(SIG_TAU, e.y, xi);
    eo.z = fmaf(SIG_TAU, e.z, xi);
    eo.w = fmaf(SIG_TAU, e.w, xi);

    ro.x = fmaf(sg4.x, eo.x, SIG_TAU * rr.x);
    ro.y = fmaf(sg4.y, eo.y, SIG_TAU * rr.y);
    ro.z = fmaf(sg4.z, eo.z, SIG_TAU * rr.z);
    ro.w = fmaf(sg4.w, eo.w, SIG_TAU * rr.w);

    Eo[v] = eo;
    Ro[v] = ro;
}

// ---------------------------------------------------------------------------
extern "C" void kernel_launch(void* const* d_in, const int* in_sizes, int n_in,
                              void* d_out, int out_size) {
    const float* x     = (const float*)d_in[0];
    const float* W     = (const float*)d_in[1];
    const float* u     = (const float*)d_in[2];
    const float* E     = (const float*)d_in[3];
    const float* R     = (const float*)d_in[4];
    const float* g_bar = (const float*)d_in[5];
    const float* ratio = (const float*)d_in[6];

    float* out       = (float*)d_out;
    float* out_s     = out;
    float* out_u     = out + N_OUT;
    float* out_E     = out + 2 * N_OUT;
    float* out_R     = out_E + (size_t)N_IN * N_OUT;
    float* out_gbar  = out_R + (size_t)N_IN * N_OUT;
    float* out_ratio = out_gbar + N_OUT;

    // K1: normal launch
    otpe_gemv_partial<<<dim3(N_OUTV / 256, NSPLIT), 256>>>((const float4*)W, x);

    // K2, K3: programmatic dependent launches with implicit completion
    // triggers (R9/R10 showed every early-trigger variant regresses).
    cudaLaunchAttribute pdl[1];
    pdl[0].id = cudaLaunchAttributeProgrammaticStreamSerialization;
    pdl[0].val.programmaticStreamSerializationAllowed = 1;

    {
        cudaLaunchConfig_t cfg = {};
        cfg.gridDim  = dim3(N_OUT / 64);
        cfg.blockDim = dim3(256);
        cfg.stream   = 0;
        cfg.attrs    = pdl;
        cfg.numAttrs = 1;
        cudaLaunchKernelEx(&cfg, otpe_reduce_post, u, g_bar, ratio,
                           out_s, out_u, out_gbar, out_ratio);
    }
    {
        const long long nvec = (long long)N_IN * N_OUT / 4;   // 8388608
        cudaLaunchConfig_t cfg = {};
        cfg.gridDim  = dim3((unsigned)(nvec / 256));
        cfg.blockDim = dim3(256);
        cfg.stream   = 0;
        cfg.attrs    = pdl;
        cfg.numAttrs = 1;
        cudaLaunchKernelEx(&cfg, otpe_big_elem,
                           (const float4*)E, (const float4*)R, x,
                           (float4*)out_E, (float4*)out_R);
    }
}